// round 3
// baseline (speedup 1.0000x reference)
#include <cuda_runtime.h>
#include <math_constants.h>

// out[b][o] = max_i min(x[b][i], w[i][o])
// x: [1024, 512] row-major, w: [512, 512] row-major, out: [1024, 512] fp32.

constexpr int B = 1024;
constexpr int I = 512;
constexpr int O = 512;

constexpr int BT = 64;   // batch tile
constexpr int OT = 64;   // out-col tile
constexpr int KT = 32;   // reduction chunk
constexpr int THREADS = 256;

__global__ __launch_bounds__(THREADS, 4)
void smooth_ste_maxmin_kernel(const float* __restrict__ x,
                              const float* __restrict__ w,
                              float* __restrict__ out) {
    __shared__ float sw[KT][OT];      // w[k][o] chunk
    __shared__ float sx[KT][BT];      // x transposed: sx[k][b]

    const int tid = threadIdx.x;
    const int o0 = blockIdx.x * OT;
    const int b0 = blockIdx.y * BT;

    // thread -> 4x4 register tile
    const int tx = tid & 15;          // o-group (4 floats)
    const int ty = tid >> 4;          // b-group (4 rows)

    float acc[4][4];
#pragma unroll
    for (int i = 0; i < 4; i++)
#pragma unroll
        for (int j = 0; j < 4; j++)
            acc[i][j] = -CUDART_INF_F;

    // loader indices
    // w chunk: KT x OT = 32 x 64 floats = 512 float4; 2 per thread
    const int wk = tid >> 4;          // 0..15 (+16 second half)
    const int wc = (tid & 15) << 2;   // col*4
    // x chunk: BT x KT = 64 x 32 floats = 512 float4; 2 per thread
    const int xb = tid & 63;          // 0..63
    const int xk4 = tid >> 6;         // 0..3 (+4 second half)

    for (int k0 = 0; k0 < I; k0 += KT) {
        // load w[k0+k][o0+c]
#pragma unroll
        for (int h = 0; h < 2; h++) {
            int k = wk + h * 16;
            float4 v = *reinterpret_cast<const float4*>(&w[(k0 + k) * O + o0 + wc]);
            *reinterpret_cast<float4*>(&sw[k][wc]) = v;
        }
        // load x[b0+xb][k0 + xk4*4 .. +3], store transposed
#pragma unroll
        for (int h = 0; h < 2; h++) {
            int k4 = xk4 + h * 4;
            float4 v = *reinterpret_cast<const float4*>(&x[(b0 + xb) * I + k0 + k4 * 4]);
            sx[k4 * 4 + 0][xb] = v.x;
            sx[k4 * 4 + 1][xb] = v.y;
            sx[k4 * 4 + 2][xb] = v.z;
            sx[k4 * 4 + 3][xb] = v.w;
        }
        __syncthreads();

#pragma unroll
        for (int k = 0; k < KT; k++) {
            float4 w4 = *reinterpret_cast<const float4*>(&sw[k][tx * 4]);
            float4 x4 = *reinterpret_cast<const float4*>(&sx[k][ty * 4]);
            float wv[4] = {w4.x, w4.y, w4.z, w4.w};
            float xv[4] = {x4.x, x4.y, x4.z, x4.w};
#pragma unroll
            for (int bi = 0; bi < 4; bi++)
#pragma unroll
                for (int oi = 0; oi < 4; oi++)
                    acc[bi][oi] = fmaxf(acc[bi][oi], fminf(xv[bi], wv[oi]));
        }
        __syncthreads();
    }

#pragma unroll
    for (int bi = 0; bi < 4; bi++) {
        int b = b0 + ty * 4 + bi;
        float4 r = make_float4(acc[bi][0], acc[bi][1], acc[bi][2], acc[bi][3]);
        *reinterpret_cast<float4*>(&out[b * O + o0 + tx * 4]) = r;
    }
}

extern "C" void kernel_launch(void* const* d_in, const int* in_sizes, int n_in,
                              void* d_out, int out_size) {
    const float* x = (const float*)d_in[0];   // [1024, 512]
    const float* w = (const float*)d_in[1];   // [512, 512]
    float* out = (float*)d_out;               // [1024, 512]

    dim3 grid(O / OT, B / BT);   // (8, 16)
    smooth_ste_maxmin_kernel<<<grid, THREADS>>>(x, w, out);
}

// round 8
// speedup vs baseline: 1.7357x; 1.7357x over previous
#include <cuda_runtime.h>
#include <cuda_fp16.h>

// out[b][o] = max_i min(x[b][i], w[i][o])
// x: [1024, 512] fp32 row-major, w: [512, 512] fp32 row-major, out: [1024, 512] fp32.
// Compute in fp16x2 (HMNMX2): exact selections of rounded inputs, rel err <= 2^-11.

constexpr int B = 1024;
constexpr int I = 512;
constexpr int O = 512;

constexpr int BT = 64;   // batch tile
constexpr int OT = 64;   // out-col tile
constexpr int KT = 64;   // reduction chunk
constexpr int THREADS = 512;

__global__ __launch_bounds__(THREADS, 1)
void maxmin_h2_kernel(const float* __restrict__ x,
                      const float* __restrict__ w,
                      float* __restrict__ out) {
    __shared__ __half  swh[KT][OT];    // w[k][o] chunk as half            (8 KB)
    __shared__ __half2 sxd[KT][BT];    // x[k][b] duplicated into half2    (16 KB)

    const int tid = threadIdx.x;
    const int o0 = blockIdx.x * OT;
    const int b0 = blockIdx.y * BT;

    // compute mapping: thread tile = 2 b-rows x 4 o-cols
    const int tx = tid & 15;          // o quad: cols tx*4 .. tx*4+3
    const int ty = tid >> 4;          // b pair: rows ty*2, ty*2+1  (0..31)

    // loader mapping
    const int wr = tid >> 3;          // w row within chunk   0..63
    const int wc = (tid & 7) * 8;     // w col group (8 floats)
    const int xb = tid & 63;          // x row (b) within tile
    const int xk = (tid >> 6) * 8;    // x col group (8 floats) 0..56

    const __half2 ninf = __half2half2(__ushort_as_half((unsigned short)0xFC00));
    __half2 acc00 = ninf, acc01 = ninf, acc10 = ninf, acc11 = ninf;

    // stage first k-tile in registers
    float4 wv0 = *reinterpret_cast<const float4*>(&w[wr * O + o0 + wc]);
    float4 wv1 = *reinterpret_cast<const float4*>(&w[wr * O + o0 + wc + 4]);
    float4 xv0 = *reinterpret_cast<const float4*>(&x[(b0 + xb) * I + xk]);
    float4 xv1 = *reinterpret_cast<const float4*>(&x[(b0 + xb) * I + xk + 4]);

    for (int k0 = 0; k0 < I; k0 += KT) {
        // ---- convert staged registers -> smem ----
        {
            __half2 h0 = __floats2half2_rn(wv0.x, wv0.y);
            __half2 h1 = __floats2half2_rn(wv0.z, wv0.w);
            __half2 h2 = __floats2half2_rn(wv1.x, wv1.y);
            __half2 h3 = __floats2half2_rn(wv1.z, wv1.w);
            uint4 pk;
            pk.x = *reinterpret_cast<unsigned*>(&h0);
            pk.y = *reinterpret_cast<unsigned*>(&h1);
            pk.z = *reinterpret_cast<unsigned*>(&h2);
            pk.w = *reinterpret_cast<unsigned*>(&h3);
            *reinterpret_cast<uint4*>(&swh[wr][wc]) = pk;   // 16B, conflict-free

            float fx[8] = {xv0.x, xv0.y, xv0.z, xv0.w, xv1.x, xv1.y, xv1.z, xv1.w};
#pragma unroll
            for (int j = 0; j < 8; j++)
                sxd[xk + j][xb] = __float2half2_rn(fx[j]);  // bank = xb%32: conflict-free
        }
        __syncthreads();

        // ---- prefetch next k-tile into registers (overlaps with compute) ----
        const int kn = (k0 + KT < I) ? (k0 + KT) : 0;
        wv0 = *reinterpret_cast<const float4*>(&w[(kn + wr) * O + o0 + wc]);
        wv1 = *reinterpret_cast<const float4*>(&w[(kn + wr) * O + o0 + wc + 4]);
        xv0 = *reinterpret_cast<const float4*>(&x[(b0 + xb) * I + kn + xk]);
        xv1 = *reinterpret_cast<const float4*>(&x[(b0 + xb) * I + kn + xk + 4]);

        // ---- main loop: 8 HMNMX2 per k per thread ----
#pragma unroll
        for (int k = 0; k < KT; k++) {
            uint2 wraw = *reinterpret_cast<const uint2*>(&swh[k][tx * 4]);   // LDS.64, broadcast
            __half2 w01 = *reinterpret_cast<__half2*>(&wraw.x);
            __half2 w23 = *reinterpret_cast<__half2*>(&wraw.y);
            uint2 xraw = *reinterpret_cast<const uint2*>(&sxd[k][ty * 2]);   // LDS.64, broadcast
            __half2 xA = *reinterpret_cast<__half2*>(&xraw.x);               // (x_b0, x_b0)
            __half2 xB = *reinterpret_cast<__half2*>(&xraw.y);               // (x_b1, x_b1)

            acc00 = __hmax2(acc00, __hmin2(xA, w01));
            acc01 = __hmax2(acc01, __hmin2(xA, w23));
            acc10 = __hmax2(acc10, __hmin2(xB, w01));
            acc11 = __hmax2(acc11, __hmin2(xB, w23));
        }
        __syncthreads();
    }

    // ---- epilogue: half2 -> fp32, coalesced float4 stores ----
    {
        int b = b0 + ty * 2;
        float4 r0 = make_float4(__low2float(acc00), __high2float(acc00),
                                __low2float(acc01), __high2float(acc01));
        float4 r1 = make_float4(__low2float(acc10), __high2float(acc10),
                                __low2float(acc11), __high2float(acc11));
        *reinterpret_cast<float4*>(&out[b * O + o0 + tx * 4]) = r0;
        *reinterpret_cast<float4*>(&out[(b + 1) * O + o0 + tx * 4]) = r1;
    }
}

extern "C" void kernel_launch(void* const* d_in, const int* in_sizes, int n_in,
                              void* d_out, int out_size) {
    const float* x = (const float*)d_in[0];   // [1024, 512]
    const float* w = (const float*)d_in[1];   // [512, 512]
    float* out = (float*)d_out;               // [1024, 512]

    dim3 grid(O / OT, B / BT);   // (8, 16) = 128 blocks, 512 threads
    maxmin_h2_kernel<<<grid, THREADS>>>(x, w, out);
}